// round 9
// baseline (speedup 1.0000x reference)
#include <cuda_runtime.h>

// SoftNCutsLoss: B=4, K=8, 32^3, radius 4 -> 251 nonzero offsets per voxel.
// Tile 4x4x32, 512 threads, 1 voxel/thread, warp = 32 consecutive z, 2 CTAs/SM.
//   sQ8[v] = uint2, 8 x e4m3 fp8 preds (LDS.64 = 2 wf) -> cvt to 4 x f16x2
//   sIp[v] = f16x2 {Is[v], Is[v+1]}, intensities PRE-SCALED by s=sqrt(log2e)/10
// Pair (dzE, dzE+1): d = Is(own)-Is(nbr); arg = fma(d, -d, C) (neg folds into
// HFMA2 modifier); ex2.f16x2 gives both affinities. Dummy hi slot: C=-inf -> 0.
// HFMA2 accumulation, chunked flush to fp32 (7 flushes). Last-CTA fused finalize.

#define EPSV 2.2204460492503131e-16f
#define TPX 10
#define TPY 10
#define TPZ 38
#define NPAD (TPX * TPY * TPZ)      // 3800
#define SMEM_BYTES (NPAD * 8 + NPAD * 4)

typedef unsigned uu;

__device__ float gPart[256 * 16];   // per-CTA partials [cta][0..7]=A, [8..15]=V
__device__ unsigned gCount;         // zero-init; last CTA resets

// ---------- compile-time fp16 constant tables ----------
constexpr unsigned short f2h(float x) {
    unsigned u = __builtin_bit_cast(unsigned, x);
    unsigned s = (u >> 16) & 0x8000u;
    int e = (int)((u >> 23) & 0xFF) - 127 + 15;
    unsigned m = u & 0x7FFFFFu;
    if (x == 0.0f) return (unsigned short)s;
    if (e >= 31) return (unsigned short)(s | 0x7C00u);      // inf
    if (e <= 0) return (unsigned short)s;                    // flush tiny
    unsigned h = s | ((unsigned)e << 10) | (m >> 13);
    unsigned rem = m & 0x1FFFu;
    if (rem > 0x1000u || (rem == 0x1000u && (h & 1u))) h++;
    return (unsigned short)h;
}
constexpr unsigned h2c(float lo, float hi) {
    return (unsigned)f2h(lo) | ((unsigned)f2h(hi) << 16);
}

struct RT {
    int voff[45];
    int m[45];
    unsigned cp[45][4];   // packed fp16 exponent constant per dz-pair
};
constexpr RT mkrt() {
    RT t{};
    const float K3 = -0.09016844005556021f;   // -log2(e)/16
    int idx = 0;
    for (int want = 3; want >= 1; want--)
        for (int dx = -3; dx <= 3; dx++)
            for (int dy = -3; dy <= 3; dy++) {
                int r2 = 16 - dx * dx - dy * dy;
                int m = 0;
                if (r2 >= 10) m = 3;
                else if (r2 >= 5) m = 2;
                else if (r2 >= 2) m = 1;
                else continue;
                if (m != want) continue;
                t.voff[idx] = dx * (TPY * TPZ) + dy * TPZ;
                t.m[idx] = m;
                int d2r = dx * dx + dy * dy;
                int jp = 0;
                for (int dzE = -m; dzE <= m; dzE += 2) {
                    float clo = (float)(d2r + dzE * dzE) * K3;
                    float chi = (float)(d2r + (dzE + 1) * (dzE + 1)) * K3;
                    bool dum = (dzE + 1 > m);
                    t.cp[idx][jp++] = dum ? ((unsigned)f2h(clo) | 0xFC000000u)  // hi=-inf
                                          : h2c(clo, chi);
                }
                idx++;
            }
    return t;
}
__constant__ RT RTT = mkrt();

// ---------- fp16 / fp8 helpers ----------
__device__ __forceinline__ uu cvt_h2(float hi, float lo) {
    uu u; asm("cvt.rn.f16x2.f32 %0, %1, %2;" : "=r"(u) : "f"(hi), "f"(lo));
    return u;
}
__device__ __forceinline__ uu ex2_h2(uu x) {
    uu r; asm("ex2.approx.f16x2 %0, %1;" : "=r"(r) : "r"(x)); return r;
}
__device__ __forceinline__ uu hsub2(uu a, uu b) {
    uu r; asm("sub.rn.f16x2 %0, %1, %2;" : "=r"(r) : "r"(a), "r"(b)); return r;
}
__device__ __forceinline__ uu hneg2(uu a) {
    uu r; asm("neg.f16x2 %0, %1;" : "=r"(r) : "r"(a)); return r;
}
__device__ __forceinline__ uu hfma2r(uu a, uu b, uu c) {
    uu r; asm("fma.rn.f16x2 %0, %1, %2, %3;" : "=r"(r) : "r"(a), "r"(b), "r"(c));
    return r;
}
__device__ __forceinline__ void hfma2(uu& acc, uu a, uu b) {
    asm("fma.rn.f16x2 %0, %1, %2, %0;" : "+r"(acc) : "r"(a), "r"(b));
}
__device__ __forceinline__ void hadd2(uu& acc, uu a) {
    asm("add.rn.f16x2 %0, %0, %1;" : "+r"(acc) : "r"(a));
}
__device__ __forceinline__ uu prmt_lo(uu x) {
    uu r; asm("prmt.b32 %0, %1, %1, 0x1010;" : "=r"(r) : "r"(x)); return r;
}
__device__ __forceinline__ uu prmt_hi(uu x) {
    uu r; asm("prmt.b32 %0, %1, %1, 0x3232;" : "=r"(r) : "r"(x)); return r;
}
// 4 f32 -> u32 of 4 e4m3 bytes [p0,p1,p2,p3]
__device__ __forceinline__ uu pack_e4m3x4(float p0, float p1, float p2, float p3) {
    uu r;
    asm("{\n\t.reg .b16 a, b;\n\t"
        "cvt.rn.satfinite.e4m3x2.f32 a, %2, %1;\n\t"
        "cvt.rn.satfinite.e4m3x2.f32 b, %4, %3;\n\t"
        "mov.b32 %0, {a, b};\n\t}"
        : "=r"(r) : "f"(p0), "f"(p1), "f"(p2), "f"(p3));
    return r;
}
// u32 of 4 e4m3 -> two f16x2
__device__ __forceinline__ void unpk_e4m3(uu q, uu& h01, uu& h23) {
    asm("{\n\t.reg .b16 l, h;\n\t"
        "mov.b32 {l, h}, %2;\n\t"
        "cvt.rn.f16x2.e4m3x2 %0, l;\n\t"
        "cvt.rn.f16x2.e4m3x2 %1, h;\n\t}"
        : "=r"(h01), "=r"(h23) : "r"(q));
}
__device__ __forceinline__ void flush_h2(uu& h, float& f0, float& f1) {
    float a, b;
    asm("{\n\t.reg .b16 l, m;\n\t"
        "mov.b32 {l, m}, %2;\n\t"
        "cvt.f32.f16 %0, l;\n\t"
        "cvt.f32.f16 %1, m;\n\t}"
        : "=f"(a), "=f"(b) : "r"(h));
    f0 += a; f1 += b; h = 0u;
}

__global__ __launch_bounds__(512, 2)
void soft_ncuts_main(const float* __restrict__ batch, const float* __restrict__ preds,
                     float* __restrict__ out) {
    extern __shared__ char smem_raw[];
    uint2*          sQ8  = (uint2*)smem_raw;                // 8 B/voxel fp8 preds
    uu*             sIp  = (uu*)(smem_raw + NPAD * 8);      // f16x2 {Is[v], Is[v+1]}
    unsigned short* sIph = (unsigned short*)sIp;

    const int tid = threadIdx.x;
    const int b   = blockIdx.y;
    const int bx  = blockIdx.x;            // 0..63
    const int ox  = (bx >> 3) * 4;
    const int oy  = (bx & 7) * 4;

    const float* batchb = batch + b * 32768;
    const float* predsb = preds + (b * 8) * 32768;

    const float SQ = 0.12011224087864498f;   // sqrt(log2(e))/10

    // zero the single never-written hi half (entry NPAD-1)
    if (tid == 0) sIph[2 * (NPAD - 1) + 1] = 0;

    // ---- stage padded 10x10x38 tile; out-of-volume = EPS ----
    for (int v = tid; v < NPAD; v += 512) {
        int px = v / (TPY * TPZ);
        int r  = v - px * (TPY * TPZ);
        int py = r / TPZ;
        int pz = r - py * TPZ;
        int gx = ox + px - 3, gy = oy + py - 3, gz = pz - 3;
        bool inb = ((unsigned)gx < 32u) && ((unsigned)gy < 32u) && ((unsigned)gz < 32u);
        int g = gx * 1024 + gy * 32 + gz;
        float I = inb ? batchb[g] : EPSV;
        float p[8];
#pragma unroll
        for (int k = 0; k < 8; k++) p[k] = inb ? predsb[k * 32768 + g] : EPSV;
        uint2 Q;
        Q.x = pack_e4m3x4(p[0], p[1], p[2], p[3]);
        Q.y = pack_e4m3x4(p[4], p[5], p[6], p[7]);
        sQ8[v] = Q;
        unsigned short Ih = (unsigned short)(cvt_h2(0.f, I * SQ) & 0xFFFFu);
        sIph[2 * v] = Ih;                    // entry v lo = Is[v]
        if (v > 0) sIph[2 * v - 1] = Ih;     // entry v-1 hi = Is[v]
    }
    __syncthreads();

    // thread -> voxel: lane = z, warp -> (wx, wy)
    const int lz = tid & 31;
    const int wy = (tid >> 5) & 3;
    const int wx = tid >> 7;
    const int v0 = (wx + 3) * (TPY * TPZ) + (wy + 3) * TPZ + (lz + 3);
    const uu  I2 = prmt_lo(sIp[v0]);        // own scaled intensity in both halves

    uu acc0 = 0, acc1 = 0, acc2 = 0, acc3 = 0, hsw = 0;
    float f[8];
#pragma unroll
    for (int k = 0; k < 8; k++) f[k] = 0.f;
    float fswE = 0.f, fswO = 0.f;

#define FLUSH()                               \
    {                                         \
        flush_h2(acc0, f[0], f[1]);           \
        flush_h2(acc1, f[2], f[3]);           \
        flush_h2(acc2, f[4], f[5]);           \
        flush_h2(acc3, f[6], f[7]);           \
        flush_h2(hsw, fswE, fswO);            \
    }

#pragma unroll
    for (int i = 0; i < 45; i++) {
        const int m  = RTT.m[i];
        const int np = m + 1;                 // pairs in this row; last has dummy hi
        const int vb = v0 + RTT.voff[i];
#pragma unroll
        for (int jp = 0; jp < 4; jp++) {
            if (jp < np) {
                const int dzE = -m + 2 * jp;
                const int vp  = vb + dzE;
                const uu ip   = sIp[vp];      // {Is[vp], Is[vp+1]}
                const uu d    = hsub2(I2, ip);
                const uu arg  = hfma2r(d, hneg2(d), RTT.cp[i][jp]);  // C - d^2
                const uu a2   = ex2_h2(arg);  // lo = a(dzE), hi = a(dzE+1) or 0
                hadd2(hsw, a2);
                const uint2 ql = sQ8[vp];     // LDS.64 fp8
                uu q01, q23, q45, q67;
                unpk_e4m3(ql.x, q01, q23);
                unpk_e4m3(ql.y, q45, q67);
                const uu aE = prmt_lo(a2);
                hfma2(acc0, aE, q01); hfma2(acc1, aE, q23);
                hfma2(acc2, aE, q45); hfma2(acc3, aE, q67);
                if (jp != np - 1) {
                    const uint2 qh = sQ8[vp + 1];
                    uu r01, r23, r45, r67;
                    unpk_e4m3(qh.x, r01, r23);
                    unpk_e4m3(qh.y, r45, r67);
                    const uu aO = prmt_hi(a2);
                    hfma2(acc0, aO, r01); hfma2(acc1, aO, r23);
                    hfma2(acc2, aO, r45); hfma2(acc3, aO, r67);
                }
            }
        }
        if (i == 5 || i == 11 || i == 17 || i == 24 || i == 31 || i == 38) FLUSH()
    }
    FLUSH()
#undef FLUSH

    const float sumw = fswE + fswO;

    // ---- epilogue: own preds exact fp32 from global ----
    const int g0 = (ox + wx) * 1024 + (oy + wy) * 32 + lz;
    float c[16];
#pragma unroll
    for (int k = 0; k < 8; k++) {
        float q = predsb[k * 32768 + g0];
        c[k]     = f[k] * q;
        c[8 + k] = sumw * q;
    }

    __shared__ float sRed[16];
    if (tid < 16) sRed[tid] = 0.f;
    __syncthreads();
#pragma unroll
    for (int j = 0; j < 16; j++) {
        float val = c[j];
#pragma unroll
        for (int o = 16; o; o >>= 1) val += __shfl_xor_sync(0xffffffffu, val, o);
        if ((tid & 31) == 0) atomicAdd(&sRed[j], val);
    }
    __syncthreads();
    if (tid < 16) gPart[(b * 64 + bx) * 16 + tid] = sRed[tid];
    __syncthreads();

    // ---- fused finalize: last CTA reduces all partials ----
    __shared__ unsigned sLast;
    if (tid == 0) {
        __threadfence();
        unsigned t = atomicAdd(&gCount, 1u);
        sLast = (t == 255u) ? 1u : 0u;
    }
    __syncthreads();
    if (sLast) {
        __shared__ float sAV[64];
        if (tid < 64) sAV[tid] = 0.f;
        __syncthreads();
        if (tid < 256) {
            const int bb = tid >> 6;            // 4
            const int jj = (tid >> 2) & 15;     // 16
            const int ch = tid & 3;             // 4 chunks of 16 CTAs
            float s = 0.f;
#pragma unroll
            for (int t2 = 0; t2 < 16; t2++)
                s += __ldcg(&gPart[(bb * 64 + ch * 16 + t2) * 16 + jj]);
            atomicAdd(&sAV[bb * 16 + jj], s);
        }
        __syncthreads();
        if (tid < 4) {
            float s2 = 0.f;
#pragma unroll
            for (int k = 0; k < 8; k++)
                s2 += sAV[tid * 16 + k] / sAV[tid * 16 + 8 + k];
            out[tid] = 8.f - s2;
        }
        if (tid == 0) gCount = 0u;
    }
}

extern "C" void kernel_launch(void* const* d_in, const int* in_sizes, int n_in,
                              void* d_out, int out_size) {
    const float* batch = (const float*)d_in[0];
    const float* preds = (const float*)d_in[1];
    float* out = (float*)d_out;

    cudaFuncSetAttribute(soft_ncuts_main, cudaFuncAttributeMaxDynamicSharedMemorySize,
                         SMEM_BYTES);

    dim3 grid(64, 4);
    soft_ncuts_main<<<grid, 512, SMEM_BYTES>>>(batch, preds, out);
}

// round 10
// speedup vs baseline: 1.0860x; 1.0860x over previous
#include <cuda_runtime.h>

// SoftNCutsLoss: B=4, K=8, 32^3, radius 4 -> 251 nonzero offsets per voxel.
// Tile 4x4x32, 512 threads, 1 voxel/thread, warp = 32 consecutive z, 2 CTAs/SM.
//   sQ[v]  = uint4, 8 x fp16 preds (LDS.128)
//   sIp[v] = f16x2 {Is[v], Is[v+1]}, intensities PRE-SCALED by sqrt(log2e)/10
// dz pairs: d = Is(own)-Is(nbr); arg = fma(d, -d, C); ex2.f16x2 -> 2 affinities.
// ALL row/pair structure is compile-time (recursive templates) -> zero
// data-dependent branches, immediate constants, immediate LDS offsets.
// HFMA2 accumulation, 7 chunked flushes to fp32. Last-CTA fused finalize.

#define EPSV 2.2204460492503131e-16f
#define TPX 10
#define TPY 10
#define TPZ 38
#define NPAD (TPX * TPY * TPZ)      // 3800
#define SMEM_BYTES (NPAD * 16 + NPAD * 4)

typedef unsigned uu;

__device__ float gPart[256 * 16];   // per-CTA partials [cta][0..7]=A, [8..15]=V
__device__ unsigned gCount;         // zero-init; last CTA resets

// ---------- compile-time fp16 constant tables ----------
constexpr unsigned short f2h(float x) {
    unsigned u = __builtin_bit_cast(unsigned, x);
    unsigned s = (u >> 16) & 0x8000u;
    int e = (int)((u >> 23) & 0xFF) - 127 + 15;
    unsigned m = u & 0x7FFFFFu;
    if (x == 0.0f) return (unsigned short)s;
    if (e >= 31) return (unsigned short)(s | 0x7C00u);      // inf
    if (e <= 0) return (unsigned short)s;                    // flush tiny
    unsigned h = s | ((unsigned)e << 10) | (m >> 13);
    unsigned rem = m & 0x1FFFu;
    if (rem > 0x1000u || (rem == 0x1000u && (h & 1u))) h++;
    return (unsigned short)h;
}
constexpr unsigned h2c(float lo, float hi) {
    return (unsigned)f2h(lo) | ((unsigned)f2h(hi) << 16);
}

struct RT {
    int voff[45];
    int m[45];
    unsigned cp[45][4];   // packed fp16 exponent constant per dz-pair
};
constexpr RT mkrt() {
    RT t{};
    const float K3 = -0.09016844005556021f;   // -log2(e)/16
    int idx = 0;
    for (int want = 3; want >= 1; want--)
        for (int dx = -3; dx <= 3; dx++)
            for (int dy = -3; dy <= 3; dy++) {
                int r2 = 16 - dx * dx - dy * dy;
                int m = 0;
                if (r2 >= 10) m = 3;
                else if (r2 >= 5) m = 2;
                else if (r2 >= 2) m = 1;
                else continue;
                if (m != want) continue;
                t.voff[idx] = dx * (TPY * TPZ) + dy * TPZ;
                t.m[idx] = m;
                int d2r = dx * dx + dy * dy;
                int jp = 0;
                for (int dzE = -m; dzE <= m; dzE += 2) {
                    float clo = (float)(d2r + dzE * dzE) * K3;
                    float chi = (float)(d2r + (dzE + 1) * (dzE + 1)) * K3;
                    bool dum = (dzE + 1 > m);
                    t.cp[idx][jp++] = dum ? ((unsigned)f2h(clo) | 0xFC000000u)  // hi=-inf
                                          : h2c(clo, chi);
                }
                idx++;
            }
    return t;
}
constexpr RT RTc = mkrt();   // compile-time only; accessed via template indices

// ---------- fp16 helpers ----------
__device__ __forceinline__ uu cvt_h2(float hi, float lo) {
    uu u; asm("cvt.rn.f16x2.f32 %0, %1, %2;" : "=r"(u) : "f"(hi), "f"(lo));
    return u;
}
__device__ __forceinline__ uu ex2_h2(uu x) {
    uu r; asm("ex2.approx.f16x2 %0, %1;" : "=r"(r) : "r"(x)); return r;
}
__device__ __forceinline__ uu hsub2(uu a, uu b) {
    uu r; asm("sub.rn.f16x2 %0, %1, %2;" : "=r"(r) : "r"(a), "r"(b)); return r;
}
__device__ __forceinline__ uu hneg2(uu a) {
    uu r; asm("neg.f16x2 %0, %1;" : "=r"(r) : "r"(a)); return r;
}
__device__ __forceinline__ uu hfma2r(uu a, uu b, uu c) {
    uu r; asm("fma.rn.f16x2 %0, %1, %2, %3;" : "=r"(r) : "r"(a), "r"(b), "r"(c));
    return r;
}
__device__ __forceinline__ void hfma2(uu& acc, uu a, uu b) {
    asm("fma.rn.f16x2 %0, %1, %2, %0;" : "+r"(acc) : "r"(a), "r"(b));
}
__device__ __forceinline__ void hadd2(uu& acc, uu a) {
    asm("add.rn.f16x2 %0, %0, %1;" : "+r"(acc) : "r"(a));
}
__device__ __forceinline__ uu prmt_lo(uu x) {
    uu r; asm("prmt.b32 %0, %1, %1, 0x1010;" : "=r"(r) : "r"(x)); return r;
}
__device__ __forceinline__ uu prmt_hi(uu x) {
    uu r; asm("prmt.b32 %0, %1, %1, 0x3232;" : "=r"(r) : "r"(x)); return r;
}
__device__ __forceinline__ void flush_h2(uu& h, float& f0, float& f1) {
    float a, b;
    asm("{\n\t.reg .b16 l, m;\n\t"
        "mov.b32 {l, m}, %2;\n\t"
        "cvt.f32.f16 %0, l;\n\t"
        "cvt.f32.f16 %1, m;\n\t}"
        : "=f"(a), "=f"(b) : "r"(h));
    f0 += a; f1 += b; h = 0u;
}

// ---------- accumulator state ----------
struct Acc {
    uu a0, a1, a2, a3, hsw;
    float f[8];
    float fe, fo;
};

__device__ __forceinline__ void flush_all(Acc& A) {
    flush_h2(A.a0, A.f[0], A.f[1]);
    flush_h2(A.a1, A.f[2], A.f[3]);
    flush_h2(A.a2, A.f[4], A.f[5]);
    flush_h2(A.a3, A.f[6], A.f[7]);
    flush_h2(A.hsw, A.fe, A.fo);
}

// ---------- fully compile-time row/pair expansion ----------
template<int I, int JP>
__device__ __forceinline__ void do_pairs(Acc& A, uu I2, const uint4* sQ,
                                         const uu* sIp, int v0) {
    constexpr int M = RTc.m[I];
    if constexpr (JP <= M) {
        constexpr int dzE  = -M + 2 * JP;
        constexpr int OFF  = RTc.voff[I] + dzE;     // compile-time LDS offset
        constexpr uu  CP   = RTc.cp[I][JP];         // immediate constant
        constexpr bool FULL = (JP < M);             // last pair has dummy hi

        const int vp  = v0 + OFF;
        const uu  ip  = sIp[vp];                    // {Is[vp], Is[vp+1]}
        const uu  d   = hsub2(I2, ip);
        const uu  arg = hfma2r(d, hneg2(d), CP);    // C - d^2 (neg folds)
        const uu  a2  = ex2_h2(arg);                // lo = a(dzE), hi = a(dzE+1)|0
        hadd2(A.hsw, a2);
        const uint4 ql = sQ[vp];
        const uu aE = prmt_lo(a2);
        hfma2(A.a0, aE, ql.x); hfma2(A.a1, aE, ql.y);
        hfma2(A.a2, aE, ql.z); hfma2(A.a3, aE, ql.w);
        if constexpr (FULL) {
            const uint4 qh = sQ[vp + 1];
            const uu aO = prmt_hi(a2);
            hfma2(A.a0, aO, qh.x); hfma2(A.a1, aO, qh.y);
            hfma2(A.a2, aO, qh.z); hfma2(A.a3, aO, qh.w);
        }
        do_pairs<I, JP + 1>(A, I2, sQ, sIp, v0);
    }
}

template<int I>
__device__ __forceinline__ void do_rows(Acc& A, uu I2, const uint4* sQ,
                                        const uu* sIp, int v0) {
    if constexpr (I < 45) {
        do_pairs<I, 0>(A, I2, sQ, sIp, v0);
        if constexpr (I == 5 || I == 11 || I == 17 || I == 24 || I == 31 || I == 38)
            flush_all(A);
        do_rows<I + 1>(A, I2, sQ, sIp, v0);
    }
}

__global__ __launch_bounds__(512, 2)
void soft_ncuts_main(const float* __restrict__ batch, const float* __restrict__ preds,
                     float* __restrict__ out) {
    extern __shared__ char smem_raw[];
    uint4*          sQ   = (uint4*)smem_raw;                // 16 B/voxel fp16 preds
    uu*             sIp  = (uu*)(smem_raw + NPAD * 16);     // f16x2 {Is[v], Is[v+1]}
    unsigned short* sIph = (unsigned short*)sIp;

    const int tid = threadIdx.x;
    const int b   = blockIdx.y;
    const int bx  = blockIdx.x;            // 0..63
    const int ox  = (bx >> 3) * 4;
    const int oy  = (bx & 7) * 4;

    const float* batchb = batch + b * 32768;
    const float* predsb = preds + (b * 8) * 32768;

    const float SQ = 0.12011224087864498f;   // sqrt(log2(e))/10

    // zero the single never-written hi half (entry NPAD-1)
    if (tid == 0) sIph[2 * (NPAD - 1) + 1] = 0;

    // ---- stage padded 10x10x38 tile; out-of-volume = EPS ----
    for (int v = tid; v < NPAD; v += 512) {
        int px = v / (TPY * TPZ);
        int r  = v - px * (TPY * TPZ);
        int py = r / TPZ;
        int pz = r - py * TPZ;
        int gx = ox + px - 3, gy = oy + py - 3, gz = pz - 3;
        bool inb = ((unsigned)gx < 32u) && ((unsigned)gy < 32u) && ((unsigned)gz < 32u);
        int g = gx * 1024 + gy * 32 + gz;
        float I = inb ? batchb[g] : EPSV;
        float p[8];
#pragma unroll
        for (int k = 0; k < 8; k++) p[k] = inb ? predsb[k * 32768 + g] : EPSV;
        uint4 Q;
        Q.x = cvt_h2(p[1], p[0]);
        Q.y = cvt_h2(p[3], p[2]);
        Q.z = cvt_h2(p[5], p[4]);
        Q.w = cvt_h2(p[7], p[6]);
        sQ[v] = Q;
        unsigned short Ih = (unsigned short)(cvt_h2(0.f, I * SQ) & 0xFFFFu);
        sIph[2 * v] = Ih;                    // entry v lo = Is[v]
        if (v > 0) sIph[2 * v - 1] = Ih;     // entry v-1 hi = Is[v]
    }
    __syncthreads();

    // thread -> voxel: lane = z, warp -> (wx, wy)
    const int lz = tid & 31;
    const int wy = (tid >> 5) & 3;
    const int wx = tid >> 7;
    const int v0 = (wx + 3) * (TPY * TPZ) + (wy + 3) * TPZ + (lz + 3);
    const uu  I2 = prmt_lo(sIp[v0]);        // own scaled intensity in both halves

    Acc A;
    A.a0 = A.a1 = A.a2 = A.a3 = A.hsw = 0u;
#pragma unroll
    for (int k = 0; k < 8; k++) A.f[k] = 0.f;
    A.fe = A.fo = 0.f;

    do_rows<0>(A, I2, sQ, sIp, v0);
    flush_all(A);

    const float sumw = A.fe + A.fo;

    // ---- epilogue: own preds exact fp32 from global ----
    const int g0 = (ox + wx) * 1024 + (oy + wy) * 32 + lz;
    float c[16];
#pragma unroll
    for (int k = 0; k < 8; k++) {
        float q = predsb[k * 32768 + g0];
        c[k]     = A.f[k] * q;
        c[8 + k] = sumw * q;
    }

    __shared__ float sRed[16];
    if (tid < 16) sRed[tid] = 0.f;
    __syncthreads();
#pragma unroll
    for (int j = 0; j < 16; j++) {
        float val = c[j];
#pragma unroll
        for (int o = 16; o; o >>= 1) val += __shfl_xor_sync(0xffffffffu, val, o);
        if ((tid & 31) == 0) atomicAdd(&sRed[j], val);
    }
    __syncthreads();
    if (tid < 16) gPart[(b * 64 + bx) * 16 + tid] = sRed[tid];
    __syncthreads();

    // ---- fused finalize: last CTA reduces all partials ----
    __shared__ unsigned sLast;
    if (tid == 0) {
        __threadfence();
        unsigned t = atomicAdd(&gCount, 1u);
        sLast = (t == 255u) ? 1u : 0u;
    }
    __syncthreads();
    if (sLast) {
        __shared__ float sAV[64];
        if (tid < 64) sAV[tid] = 0.f;
        __syncthreads();
        if (tid < 256) {
            const int bb = tid >> 6;            // 4
            const int jj = (tid >> 2) & 15;     // 16
            const int ch = tid & 3;             // 4 chunks of 16 CTAs
            float s = 0.f;
#pragma unroll
            for (int t2 = 0; t2 < 16; t2++)
                s += __ldcg(&gPart[(bb * 64 + ch * 16 + t2) * 16 + jj]);
            atomicAdd(&sAV[bb * 16 + jj], s);
        }
        __syncthreads();
        if (tid < 4) {
            float s2 = 0.f;
#pragma unroll
            for (int k = 0; k < 8; k++)
                s2 += sAV[tid * 16 + k] / sAV[tid * 16 + 8 + k];
            out[tid] = 8.f - s2;
        }
        if (tid == 0) gCount = 0u;
    }
}

extern "C" void kernel_launch(void* const* d_in, const int* in_sizes, int n_in,
                              void* d_out, int out_size) {
    const float* batch = (const float*)d_in[0];
    const float* preds = (const float*)d_in[1];
    float* out = (float*)d_out;

    cudaFuncSetAttribute(soft_ncuts_main, cudaFuncAttributeMaxDynamicSharedMemorySize,
                         SMEM_BYTES);

    dim3 grid(64, 4);
    soft_ncuts_main<<<grid, 512, SMEM_BYTES>>>(batch, preds, out);
}